// round 3
// baseline (speedup 1.0000x reference)
#include <cuda_runtime.h>
#include <cstddef>

#define Bb 8
#define Hh 16
#define Ll 1024
#define Dd 64
#define BH (Bb*Hh)          // 128
#define DMODEL (Hh*Dd)      // 1024

// scratch (no allocations allowed)
__device__ float g_gate[BH*Ll];            // [bh][k]
__device__ float g_invsum[BH*Ll];          // [bh][q]
__device__ float g_attnout[BH*Ll*Dd];      // [bh][l][d], normalized

// ---------------------------------------------------------------------------
// K1: gate[b,h,k] = sigmoid( tanh(pt @ W1^T + b1) . w2 + b2 )
// one warp per (b,h,k) row
// ---------------------------------------------------------------------------
__global__ __launch_bounds__(256) void gate_kernel(
    const float* __restrict__ pt, const float* __restrict__ W1,
    const float* __restrict__ b1, const float* __restrict__ w2,
    const float* __restrict__ b2)
{
    __shared__ float W1s[64][65];
    __shared__ float w2s[64];
    __shared__ float b1s[64];
    __shared__ float pts[8][64];

    const int tid = threadIdx.x;
    for (int i = tid; i < 64*64; i += 256) W1s[i >> 6][i & 63] = W1[i];
    if (tid < 64) { w2s[tid] = w2[tid]; b1s[tid] = b1[tid]; }
    __syncthreads();

    const int warp = tid >> 5, lane = tid & 31;
    const size_t row = (size_t)blockIdx.x * 8 + warp;   // 0..131071
    const float* p = pt + row * Dd;
    pts[warp][lane]      = p[lane];
    pts[warp][lane + 32] = p[lane + 32];
    __syncwarp();

    float acc0 = 0.f, acc1 = 0.f;
#pragma unroll
    for (int d = 0; d < 64; d++) {
        float x = pts[warp][d];
        acc0 = fmaf(x, W1s[lane][d],      acc0);
        acc1 = fmaf(x, W1s[lane + 32][d], acc1);
    }
    float t0 = tanhf(acc0 + b1s[lane]);
    float t1 = tanhf(acc1 + b1s[lane + 32]);
    float part = t0 * w2s[lane] + t1 * w2s[lane + 32];
#pragma unroll
    for (int off = 16; off > 0; off >>= 1)
        part += __shfl_xor_sync(0xffffffffu, part, off);
    if (lane == 0)
        g_gate[row] = 1.0f / (1.0f + __expf(-(part + b2[0])));
}

// ---------------------------------------------------------------------------
// K2a: for each (bh, 64-q tile):
//   loop over 16 k-tiles of 64:
//     scores = (q*scale) @ k^T + bias ; e = exp(scores)
//     rowsum += e ; w = e*gate[k] ; write w to weights (unnormalized)
//     O += w @ v
//   write invsum, write O/rowsum to g_attnout
// 256 threads, 4x4 register micro-tiles
// ---------------------------------------------------------------------------
__global__ __launch_bounds__(256) void attn_kernel(
    const float* __restrict__ q, const float* __restrict__ k,
    const float* __restrict__ v, const float* __restrict__ bias,
    float* __restrict__ wout)
{
    extern __shared__ float sm[];
    float* qs = sm;                 // 64 x 65
    float* ks = sm + 64*65;         // 64 x 65
    float* vs = sm + 2*64*65;       // 64 x 65
    float* ps = sm + 3*64*65;       // 64 x 65
    float* gs = sm + 4*64*65;       // 64

    const int tid = threadIdx.x;
    const int tx = tid & 15, ty = tid >> 4;
    const int bh = blockIdx.y;
    const int q0 = blockIdx.x * 64;

    const size_t qkv_base = (size_t)bh * Ll * Dd;
    {
        const float* qp = q + qkv_base + (size_t)q0 * Dd;
        for (int i = tid; i < 64*64; i += 256) {
            int r = i >> 6, c = i & 63;
            qs[r*65 + c] = qp[i] * 0.125f;     // 1/sqrt(64)
        }
    }

    float rsum[4] = {0.f, 0.f, 0.f, 0.f};
    float oacc[4][4];
#pragma unroll
    for (int i = 0; i < 4; i++)
#pragma unroll
        for (int j = 0; j < 4; j++) oacc[i][j] = 0.f;

    const size_t bw_base = (size_t)bh * Ll * Ll + (size_t)q0 * Ll;
    const float* biasp = bias + bw_base;
    float* wp = wout + bw_base;

    __syncthreads();

    for (int kt = 0; kt < 16; kt++) {
        {
            const float* kp = k + qkv_base + (size_t)kt * 64 * Dd;
            const float* vp = v + qkv_base + (size_t)kt * 64 * Dd;
            for (int i = tid; i < 64*64; i += 256) {
                int r = i >> 6, c = i & 63;
                ks[r*65 + c] = kp[i];
                vs[r*65 + c] = vp[i];
            }
            if (tid < 64) gs[tid] = g_gate[(size_t)bh * Ll + kt*64 + tid];
        }
        __syncthreads();

        // scores micro-GEMM
        float acc[4][4];
#pragma unroll
        for (int i = 0; i < 4; i++)
#pragma unroll
            for (int j = 0; j < 4; j++) acc[i][j] = 0.f;

#pragma unroll 8
        for (int d = 0; d < 64; d++) {
            float a[4], bb[4];
#pragma unroll
            for (int i = 0; i < 4; i++) a[i]  = qs[(ty*4 + i)*65 + d];
#pragma unroll
            for (int j = 0; j < 4; j++) bb[j] = ks[(tx*4 + j)*65 + d];
#pragma unroll
            for (int i = 0; i < 4; i++)
#pragma unroll
                for (int j = 0; j < 4; j++)
                    acc[i][j] = fmaf(a[i], bb[j], acc[i][j]);
        }

        // epilogue: bias, exp, gate, write weights (unnormalized) + smem P
#pragma unroll
        for (int i = 0; i < 4; i++) {
            const int qr  = ty*4 + i;
            const int kc0 = tx*4;
            float4 bv = *reinterpret_cast<const float4*>(
                biasp + (size_t)qr * Ll + kt*64 + kc0);
            float e0 = __expf(acc[i][0] + bv.x);
            float e1 = __expf(acc[i][1] + bv.y);
            float e2 = __expf(acc[i][2] + bv.z);
            float e3 = __expf(acc[i][3] + bv.w);
            rsum[i] += (e0 + e1) + (e2 + e3);
            float4 wv;
            wv.x = e0 * gs[kc0 + 0];
            wv.y = e1 * gs[kc0 + 1];
            wv.z = e2 * gs[kc0 + 2];
            wv.w = e3 * gs[kc0 + 3];
            ps[qr*65 + kc0 + 0] = wv.x;
            ps[qr*65 + kc0 + 1] = wv.y;
            ps[qr*65 + kc0 + 2] = wv.z;
            ps[qr*65 + kc0 + 3] = wv.w;
            *reinterpret_cast<float4*>(wp + (size_t)qr * Ll + kt*64 + kc0) = wv;
        }
        __syncthreads();

        // O += P @ V  (tx now indexes d-groups)
#pragma unroll 8
        for (int kk = 0; kk < 64; kk++) {
            float a[4], bb[4];
#pragma unroll
            for (int i = 0; i < 4; i++) a[i]  = ps[(ty*4 + i)*65 + kk];
#pragma unroll
            for (int j = 0; j < 4; j++) bb[j] = vs[kk*65 + tx*4 + j];
#pragma unroll
            for (int i = 0; i < 4; i++)
#pragma unroll
                for (int j = 0; j < 4; j++)
                    oacc[i][j] = fmaf(a[i], bb[j], oacc[i][j]);
        }
        __syncthreads();
    }

    // reduce rowsum across the 16 tx lanes sharing each q row
#pragma unroll
    for (int i = 0; i < 4; i++) {
        float r = rsum[i];
        r += __shfl_xor_sync(0xffffffffu, r, 1);
        r += __shfl_xor_sync(0xffffffffu, r, 2);
        r += __shfl_xor_sync(0xffffffffu, r, 4);
        r += __shfl_xor_sync(0xffffffffu, r, 8);
        rsum[i] = r;
    }
    if (tx == 0) {
#pragma unroll
        for (int i = 0; i < 4; i++)
            g_invsum[(size_t)bh * Ll + q0 + ty*4 + i] = 1.0f / rsum[i];
    }
#pragma unroll
    for (int i = 0; i < 4; i++) {
        float inv = 1.0f / rsum[i];
        float4 ov;
        ov.x = oacc[i][0] * inv;
        ov.y = oacc[i][1] * inv;
        ov.z = oacc[i][2] * inv;
        ov.w = oacc[i][3] * inv;
        *reinterpret_cast<float4*>(
            g_attnout + ((size_t)bh * Ll + q0 + ty*4 + i) * Dd + tx*4) = ov;
    }
}

// ---------------------------------------------------------------------------
// K2b: weights row normalize (w *= invsum[row]); one block per row
// ---------------------------------------------------------------------------
__global__ __launch_bounds__(256) void normalize_kernel(float* __restrict__ w)
{
    const size_t row = blockIdx.x;
    const float inv = g_invsum[row];
    float4* p = reinterpret_cast<float4*>(w + row * Ll);
    float4 x = p[threadIdx.x];
    x.x *= inv; x.y *= inv; x.z *= inv; x.w *= inv;
    p[threadIdx.x] = x;
}

// ---------------------------------------------------------------------------
// K3: graph_out[b,l,:] = concat_h attnout[b,h,l,:] @ W_out^T + b_out
// tiled 64x64, K-steps of 32, 4x4 register micro-tiles
// ---------------------------------------------------------------------------
__global__ __launch_bounds__(256) void outproj_kernel(
    const float* __restrict__ W, const float* __restrict__ bo,
    float* __restrict__ out)
{
    __shared__ float As[64][33];
    __shared__ float Ws[64][33];

    const int tid = threadIdx.x;
    const int tx = tid & 15, ty = tid >> 4;
    const int n0   = blockIdx.x * 64;
    const int row0 = blockIdx.y * 64;      // global m = b*1024 + l
    const int b  = row0 >> 10;
    const int l0 = row0 & 1023;

    float acc[4][4];
#pragma unroll
    for (int i = 0; i < 4; i++)
#pragma unroll
        for (int j = 0; j < 4; j++) acc[i][j] = 0.f;

    for (int kt = 0; kt < 32; kt++) {
        const int kg0 = kt * 32;
        const int h   = kg0 >> 6;
        const int dd0 = kg0 & 63;
        const float* ap = g_attnout
            + ((size_t)(b * Hh + h) * Ll + l0) * Dd + dd0;
        for (int i = tid; i < 64*32; i += 256) {
            int r = i >> 5, c = i & 31;
            As[r][c] = ap[(size_t)r * Dd + c];
        }
        const float* wpp = W + (size_t)n0 * DMODEL + kg0;
        for (int i = tid; i < 64*32; i += 256) {
            int r = i >> 5, c = i & 31;
            Ws[r][c] = wpp[(size_t)r * DMODEL + c];
        }
        __syncthreads();

#pragma unroll 8
        for (int c = 0; c < 32; c++) {
            float a[4], bb[4];
#pragma unroll
            for (int i = 0; i < 4; i++) a[i]  = As[ty*4 + i][c];
#pragma unroll
            for (int j = 0; j < 4; j++) bb[j] = Ws[tx*4 + j][c];
#pragma unroll
            for (int i = 0; i < 4; i++)
#pragma unroll
                for (int j = 0; j < 4; j++)
                    acc[i][j] = fmaf(a[i], bb[j], acc[i][j]);
        }
        __syncthreads();
    }

#pragma unroll
    for (int i = 0; i < 4; i++) {
        const int m = row0 + ty*4 + i;
        float4 ov;
        ov.x = acc[i][0] + bo[n0 + tx*4 + 0];
        ov.y = acc[i][1] + bo[n0 + tx*4 + 1];
        ov.z = acc[i][2] + bo[n0 + tx*4 + 2];
        ov.w = acc[i][3] + bo[n0 + tx*4 + 3];
        *reinterpret_cast<float4*>(out + (size_t)m * DMODEL + n0 + tx*4) = ov;
    }
}

// ---------------------------------------------------------------------------
extern "C" void kernel_launch(void* const* d_in, const int* in_sizes, int n_in,
                              void* d_out, int out_size)
{
    const float* q    = (const float*)d_in[0];
    const float* k    = (const float*)d_in[1];
    const float* v    = (const float*)d_in[2];
    const float* pt   = (const float*)d_in[3];
    const float* bias = (const float*)d_in[4];
    const float* W1   = (const float*)d_in[5];
    const float* b1   = (const float*)d_in[6];
    const float* w2   = (const float*)d_in[7];
    const float* b2   = (const float*)d_in[8];
    const float* Wo   = (const float*)d_in[9];
    const float* bo   = (const float*)d_in[10];

    float* graph_out = (float*)d_out;                               // [8,1024,1024]
    float* weights   = (float*)d_out + (size_t)Bb * Ll * DMODEL;    // [8,16,1024,1024]

    const int attn_smem = (4 * 64 * 65 + 64) * (int)sizeof(float);  // 66816 B
    cudaFuncSetAttribute(attn_kernel,
                         cudaFuncAttributeMaxDynamicSharedMemorySize, attn_smem);

    gate_kernel<<<BH * Ll / 8, 256>>>(pt, W1, b1, w2, b2);
    attn_kernel<<<dim3(Ll / 64, BH), 256, attn_smem>>>(q, k, v, bias, weights);
    normalize_kernel<<<BH * Ll, 256>>>(weights);
    outproj_kernel<<<dim3(DMODEL / 64, Bb * Ll / 64), 256>>>(Wo, bo, graph_out);
}